// round 13
// baseline (speedup 1.0000x reference)
#include <cuda_runtime.h>

#define KDIM  32
#define TABN  1024
#define COEF  0.3989422804014327f
#define EPS   2.220446049250313e-16f

#define G     128
#define XMIN  (-6.5f)
#define XMAX  (6.5f)
#define DX    ((XMAX - XMIN) / (G - 1))
#define DXI   ((G - 1) / (XMAX - XMIN))
#define TSTRIDE 128
#define TFLOATS (G * TSTRIDE)

#define NBLK  148
#define NTHR  1024
#define NGRP  16

__device__ __align__(16) float d_T[TFLOATS];    // loglik grid [x1][x0]

// Two-level barrier state. Root resets everything before release, and the
// next launch cannot start until this kernel exits -> replay-safe.
__device__ unsigned int g_cnt0[NGRP * 32];      // group counters, 128B apart
__device__ unsigned int g_root;
__device__ volatile unsigned int g_flag;        // monotonic epoch

__device__ __forceinline__ float ex2(float x) {
    float r;
    asm("ex2.approx.ftz.f32 %0, %1;" : "=f"(r) : "f"(x));
    return r;
}

__global__ __launch_bounds__(NTHR)
void fused_kernel(const float2* __restrict__ X, float* __restrict__ out,
                  const float* __restrict__ Wk0, const float* __restrict__ W10,
                  const float* __restrict__ W21, const float* __restrict__ mu,
                  const float* __restrict__ sigma, int N) {
    int tid  = threadIdx.x;
    int bid  = blockIdx.x;
    int gtid = bid * NTHR + tid;
    int lane = tid & 31;
    int w    = tid >> 5;

    // ---- Phase 0: prefetch my sample; DRAM latency overlaps table build ---
    float2 p = make_float2(0.f, 0.f);
    if (gtid < N) p = __ldg(&X[gtid]);

    // ---- Phase A+B: blocks 0..63 each build one 16x16 tile of T ----------
    __shared__ float t10[32 * 33], t21[32 * 33];
    __shared__ float s10[KDIM], s21[KDIM], w0n[KDIM];
    __shared__ float wcg[TABN], wch[TABN], smu[TABN], sinv[TABN];
    __shared__ float shh[16][33], shg[16][33];

    if (bid < 64) {
        float v10 = W10[tid];
        float v21 = W21[tid];
        float m   = mu[tid];
        float s   = sigma[tid];
        float vk0 = (w == 0) ? Wk0[lane] : 0.f;

        float e10 = expf(v10);
        float e21 = expf(v21);
        t10[lane * 33 + w] = e10;          // transposed: column b contiguous
        t21[lane * 33 + w] = e21;
        __syncthreads();

        {   // softmax(axis 0) column sums via per-warp shuffle trees
            float a10 = t10[w * 33 + lane];
            float a21 = t21[w * 33 + lane];
#pragma unroll
            for (int d = 16; d > 0; d >>= 1) {
                a10 += __shfl_xor_sync(0xFFFFFFFFu, a10, d);
                a21 += __shfl_xor_sync(0xFFFFFFFFu, a21, d);
            }
            if (lane == 0) { s10[w] = a10; s21[w] = a21; }
        }
        if (w == 0) {
            float e0 = expf(vk0);
            float sum = e0;
#pragma unroll
            for (int d = 16; d > 0; d >>= 1)
                sum += __shfl_xor_sync(0xFFFFFFFFu, sum, d);
            w0n[lane] = e0 / sum;
        }
        __syncthreads();

        {
            int b = tid & 31;
            float inv = 1.0f / s;
            smu[tid]  = m;
            sinv[tid] = inv;
            wcg[tid] = (e21 / s21[b]) * COEF * inv;            // w21n*coef/sig
            wch[tid] = (e10 / s10[b]) * w0n[b] * COEF * inv;   // w10n*w0*coef/sig
        }
        __syncthreads();

        // Basis rows for this tile (1024 values, 1/thread, 32 ex2 each)
        int bi0 = bid & 7;
        int bi1 = bid >> 3;
        const float K2 = -0.72134752044448170f;    // -0.5*log2(e)
        {
            int half = tid >> 9;       // 0: h (x0 rows), 1: g (x1 rows)
            int rr   = (tid >> 5) & 15;
            int a    = tid & 31;
            float acc = 0.f;
            if (half == 0) {
                float x = XMIN + (float)(bi0 * 16 + rr) * DX;
#pragma unroll
                for (int mm = 0; mm < KDIM; mm++) {
                    int bb = (mm + a) & 31;        // skew: conflict-free
                    int e = a * KDIM + bb;
                    float z = (x - smu[e]) * sinv[e];
                    acc += wch[e] * ex2(K2 * z * z);
                }
                shh[rr][a] = acc;
            } else {
                float x = XMIN + (float)(bi1 * 16 + rr) * DX;
#pragma unroll
                for (int mm = 0; mm < KDIM; mm++) {
                    int e = mm * KDIM + a;
                    float z = (x - smu[e]) * sinv[e];
                    acc += wcg[e] * ex2(K2 * z * z);
                }
                shg[rr][a] = acc;
            }
        }
        __syncthreads();

        if (tid < 256) {
            int li0 = tid & 15;
            int li1 = tid >> 4;
            float acc = 0.f;
#pragma unroll
            for (int a = 0; a < KDIM; a++)
                acc = fmaf(shh[li0][a], shg[li1][a], acc);
            d_T[(bi1 * 16 + li1) * TSTRIDE + (bi0 * 16 + li0)] =
                logf(acc + EPS);
        }
    }

    // ---- Grid barrier: two-level arrival tree, single epoch flag ---------
    __threadfence();               // publish my d_T stores (and order reads)
    __syncthreads();               // whole block's fences complete
    if (tid == 0) {
        unsigned int e = g_flag;   // read BEFORE own arrival -> pre-release
        int grp  = bid & (NGRP - 1);
        unsigned int gsz = 9u + (grp < (NBLK & (NGRP - 1)) ? 1u : 0u);
        if (atomicAdd(&g_cnt0[grp * 32], 1u) == gsz - 1u) {
            if (atomicAdd(&g_root, 1u) == NGRP - 1u) {
                // Last block chip-wide: reset state, then release.
#pragma unroll
                for (int g = 0; g < NGRP; g++) g_cnt0[g * 32] = 0u;
                g_root = 0u;
                __threadfence();
                g_flag = e + 1u;
            }
        }
        while (g_flag == e) __nanosleep(32);
    }
    __syncthreads();

    // ---- Phase C: bicubic interpolation (X already in registers) ---------
    if (gtid < N) {
        float u0 = fminf(fmaxf((p.x - XMIN) * DXI, 1.0f), (float)(G - 3) + 0.999f);
        float u1 = fminf(fmaxf((p.y - XMIN) * DXI, 1.0f), (float)(G - 3) + 0.999f);
        int j0 = (int)u0;
        int j1 = (int)u1;
        float t0 = u0 - (float)j0;
        float t1 = u1 - (float)j1;

        const float* bp = d_T + (j1 - 1) * TSTRIDE + (j0 - 1);
        float v[16];
#pragma unroll
        for (int rr = 0; rr < 4; rr++)
#pragma unroll
            for (int cc = 0; cc < 4; cc++)
                v[rr * 4 + cc] = __ldg(bp + rr * TSTRIDE + cc);

        float am = t0 - 1.f, bm = t0 - 2.f, cp = t0 + 1.f;
        float wx0 = -t0 * am * bm * (1.f / 6.f);
        float wx1 = cp * am * bm * 0.5f;
        float wx2 = -cp * t0 * bm * 0.5f;
        float wx3 = cp * t0 * am * (1.f / 6.f);
        am = t1 - 1.f; bm = t1 - 2.f; cp = t1 + 1.f;
        float wy0 = -t1 * am * bm * (1.f / 6.f);
        float wy1 = cp * am * bm * 0.5f;
        float wy2 = -cp * t1 * bm * 0.5f;
        float wy3 = cp * t1 * am * (1.f / 6.f);

        float r0 = fmaf(wx0, v[0],  fmaf(wx1, v[1],  fmaf(wx2, v[2],  wx3 * v[3])));
        float r1 = fmaf(wx0, v[4],  fmaf(wx1, v[5],  fmaf(wx2, v[6],  wx3 * v[7])));
        float r2 = fmaf(wx0, v[8],  fmaf(wx1, v[9],  fmaf(wx2, v[10], wx3 * v[11])));
        float r3 = fmaf(wx0, v[12], fmaf(wx1, v[13], fmaf(wx2, v[14], wx3 * v[15])));

        out[gtid] = fmaf(wy0, r0, fmaf(wy1, r1, fmaf(wy2, r2, wy3 * r3)));
    }
}

extern "C" void kernel_launch(void* const* d_in, const int* in_sizes, int n_in,
                              void* d_out, int out_size) {
    const float* X     = (const float*)d_in[0];
    const float* Wk0   = (const float*)d_in[1];
    const float* W10   = (const float*)d_in[2];
    const float* W21   = (const float*)d_in[3];
    const float* mu    = (const float*)d_in[4];
    const float* sigma = (const float*)d_in[5];
    int N = in_sizes[0] / 2;

    fused_kernel<<<NBLK, NTHR>>>((const float2*)X, (float*)d_out,
                                 Wk0, W10, W21, mu, sigma, N);
}

// round 14
// speedup vs baseline: 2.1254x; 2.1254x over previous
#include <cuda_runtime.h>

#define KDIM  32
#define TABN  1024
#define COEF  0.3989422804014327f
#define EPS   2.220446049250313e-16f

#define G     64
#define XMIN  (-6.5f)
#define XMAX  (6.5f)
#define DX    ((XMAX - XMIN) / (G - 1))
#define DXI   ((G - 1) / (XMAX - XMIN))
#define TSTRIDE 64
#define TFLOATS (G * TSTRIDE)          // 4096 floats = 16 KB

__device__ __align__(16) float d_T[TFLOATS];   // loglik grid [x1][x0]

__device__ __forceinline__ float ex2(float x) {
    float r;
    asm("ex2.approx.ftz.f32 %0, %1;" : "=f"(r) : "f"(x));
    return r;
}

// ---------------- Build: weights + basis + one 16x16 T-tile per block ------
// 16 blocks x 1024 threads. Each block redundantly computes softmax weights
// (shuffle trees), per-entry constants, then the 16 h-rows + 16 g-rows its
// tile needs (1 basis value/thread, 32 ex2), then 256 dot+log outputs.
__global__ __launch_bounds__(1024)
void build_T_kernel(const float* __restrict__ Wk0,
                    const float* __restrict__ W10,
                    const float* __restrict__ W21,
                    const float* __restrict__ mu,
                    const float* __restrict__ sigma) {
    __shared__ float t10[32 * 33], t21[32 * 33];
    __shared__ float s10[KDIM], s21[KDIM], w0n[KDIM];
    __shared__ float wcg[TABN], wch[TABN], smu[TABN], sinv[TABN];
    __shared__ float shh[16][33], shg[16][33];

    int tid  = threadIdx.x;
    int w    = tid >> 5;
    int lane = tid & 31;

    float v10 = W10[tid];
    float v21 = W21[tid];
    float m   = mu[tid];
    float s   = sigma[tid];
    float vk0 = (w == 0) ? Wk0[lane] : 0.f;

    float e10 = expf(v10);
    float e21 = expf(v21);
    t10[lane * 33 + w] = e10;            // transposed: column contiguous
    t21[lane * 33 + w] = e21;
    __syncthreads();

    {   // softmax(axis 0) column sums via per-warp shuffle trees
        float a10 = t10[w * 33 + lane];
        float a21 = t21[w * 33 + lane];
#pragma unroll
        for (int d = 16; d > 0; d >>= 1) {
            a10 += __shfl_xor_sync(0xFFFFFFFFu, a10, d);
            a21 += __shfl_xor_sync(0xFFFFFFFFu, a21, d);
        }
        if (lane == 0) { s10[w] = a10; s21[w] = a21; }
    }
    if (w == 0) {
        float e0 = expf(vk0);
        float sum = e0;
#pragma unroll
        for (int d = 16; d > 0; d >>= 1)
            sum += __shfl_xor_sync(0xFFFFFFFFu, sum, d);
        w0n[lane] = e0 / sum;
    }
    __syncthreads();

    {
        int b = tid & 31;
        float inv = 1.0f / s;
        smu[tid]  = m;
        sinv[tid] = inv;
        wcg[tid] = (e21 / s21[b]) * COEF * inv;            // w21n*coef/sigma
        wch[tid] = (e10 / s10[b]) * w0n[b] * COEF * inv;   // w10n*w0*coef/sigma
    }
    __syncthreads();

    int bi0 = blockIdx.x & 3;            // 4x4 tiles of 16x16
    int bi1 = blockIdx.x >> 2;
    const float K2 = -0.72134752044448170f;   // -0.5*log2(e)
    {
        int half = tid >> 9;             // 0: h (x0 rows), 1: g (x1 rows)
        int rr   = (tid >> 5) & 15;
        int a    = tid & 31;
        float acc = 0.f;
        if (half == 0) {
            float x = XMIN + (float)(bi0 * 16 + rr) * DX;
#pragma unroll
            for (int mm = 0; mm < KDIM; mm++) {
                int bb = (mm + a) & 31;  // skew: conflict-free smem
                int e = a * KDIM + bb;
                float z = (x - smu[e]) * sinv[e];
                acc += wch[e] * ex2(K2 * z * z);
            }
            shh[rr][a] = acc;
        } else {
            float x = XMIN + (float)(bi1 * 16 + rr) * DX;
#pragma unroll
            for (int mm = 0; mm < KDIM; mm++) {
                int e = mm * KDIM + a;
                float z = (x - smu[e]) * sinv[e];
                acc += wcg[e] * ex2(K2 * z * z);
            }
            shg[rr][a] = acc;
        }
    }
    __syncthreads();

    if (tid < 256) {
        int li0 = tid & 15;
        int li1 = tid >> 4;
        float acc = 0.f;
#pragma unroll
        for (int a = 0; a < KDIM; a++)
            acc = fmaf(shh[li0][a], shg[li1][a], acc);
        d_T[(bi1 * 16 + li1) * TSTRIDE + (bi0 * 16 + li0)] = logf(acc + EPS);
    }
}

// ---------------- Interp: 2 samples/thread, 32-deep load batch -------------
__global__ __launch_bounds__(128)
void interp_kernel(const float4* __restrict__ X4, const float2* __restrict__ X2,
                   float* __restrict__ out, int N) {
    int t = blockIdx.x * 128 + threadIdx.x;
    int n0 = 2 * t;
    if (n0 >= N) return;

    if (n0 + 1 < N) {
        float4 q = __ldg(&X4[t]);        // samples n0 (q.x,q.y), n0+1 (q.z,q.w)

        // Index setup for both samples
        float uA0 = fminf(fmaxf((q.x - XMIN) * DXI, 1.0f), (float)(G - 3) + 0.999f);
        float uA1 = fminf(fmaxf((q.y - XMIN) * DXI, 1.0f), (float)(G - 3) + 0.999f);
        float uB0 = fminf(fmaxf((q.z - XMIN) * DXI, 1.0f), (float)(G - 3) + 0.999f);
        float uB1 = fminf(fmaxf((q.w - XMIN) * DXI, 1.0f), (float)(G - 3) + 0.999f);
        int jA0 = (int)uA0, jA1 = (int)uA1, jB0 = (int)uB0, jB1 = (int)uB1;
        float tA0 = uA0 - (float)jA0, tA1 = uA1 - (float)jA1;
        float tB0 = uB0 - (float)jB0, tB1 = uB1 - (float)jB1;

        const float* bpA = d_T + (jA1 - 1) * TSTRIDE + (jA0 - 1);
        const float* bpB = d_T + (jB1 - 1) * TSTRIDE + (jB0 - 1);

        // Issue all 32 independent loads before any math (32-deep MLP)
        float vA[16], vB[16];
#pragma unroll
        for (int rr = 0; rr < 4; rr++)
#pragma unroll
            for (int cc = 0; cc < 4; cc++)
                vA[rr * 4 + cc] = __ldg(bpA + rr * TSTRIDE + cc);
#pragma unroll
        for (int rr = 0; rr < 4; rr++)
#pragma unroll
            for (int cc = 0; cc < 4; cc++)
                vB[rr * 4 + cc] = __ldg(bpB + rr * TSTRIDE + cc);

        // Weights + combine, sample A
        float am = tA0 - 1.f, bm = tA0 - 2.f, cp = tA0 + 1.f;
        float wx0 = -tA0 * am * bm * (1.f / 6.f);
        float wx1 = cp * am * bm * 0.5f;
        float wx2 = -cp * tA0 * bm * 0.5f;
        float wx3 = cp * tA0 * am * (1.f / 6.f);
        am = tA1 - 1.f; bm = tA1 - 2.f; cp = tA1 + 1.f;
        float wy0 = -tA1 * am * bm * (1.f / 6.f);
        float wy1 = cp * am * bm * 0.5f;
        float wy2 = -cp * tA1 * bm * 0.5f;
        float wy3 = cp * tA1 * am * (1.f / 6.f);
        float r0 = fmaf(wx0, vA[0],  fmaf(wx1, vA[1],  fmaf(wx2, vA[2],  wx3 * vA[3])));
        float r1 = fmaf(wx0, vA[4],  fmaf(wx1, vA[5],  fmaf(wx2, vA[6],  wx3 * vA[7])));
        float r2 = fmaf(wx0, vA[8],  fmaf(wx1, vA[9],  fmaf(wx2, vA[10], wx3 * vA[11])));
        float r3 = fmaf(wx0, vA[12], fmaf(wx1, vA[13], fmaf(wx2, vA[14], wx3 * vA[15])));
        float outA = fmaf(wy0, r0, fmaf(wy1, r1, fmaf(wy2, r2, wy3 * r3)));

        // Weights + combine, sample B
        am = tB0 - 1.f; bm = tB0 - 2.f; cp = tB0 + 1.f;
        wx0 = -tB0 * am * bm * (1.f / 6.f);
        wx1 = cp * am * bm * 0.5f;
        wx2 = -cp * tB0 * bm * 0.5f;
        wx3 = cp * tB0 * am * (1.f / 6.f);
        am = tB1 - 1.f; bm = tB1 - 2.f; cp = tB1 + 1.f;
        wy0 = -tB1 * am * bm * (1.f / 6.f);
        wy1 = cp * am * bm * 0.5f;
        wy2 = -cp * tB1 * bm * 0.5f;
        wy3 = cp * tB1 * am * (1.f / 6.f);
        r0 = fmaf(wx0, vB[0],  fmaf(wx1, vB[1],  fmaf(wx2, vB[2],  wx3 * vB[3])));
        r1 = fmaf(wx0, vB[4],  fmaf(wx1, vB[5],  fmaf(wx2, vB[6],  wx3 * vB[7])));
        r2 = fmaf(wx0, vB[8],  fmaf(wx1, vB[9],  fmaf(wx2, vB[10], wx3 * vB[11])));
        r3 = fmaf(wx0, vB[12], fmaf(wx1, vB[13], fmaf(wx2, vB[14], wx3 * vB[15])));
        float outB = fmaf(wy0, r0, fmaf(wy1, r1, fmaf(wy2, r2, wy3 * r3)));

        *(float2*)(out + n0) = make_float2(outA, outB);
    } else {
        // Tail: single sample
        float2 p = __ldg(&X2[n0]);
        float u0 = fminf(fmaxf((p.x - XMIN) * DXI, 1.0f), (float)(G - 3) + 0.999f);
        float u1 = fminf(fmaxf((p.y - XMIN) * DXI, 1.0f), (float)(G - 3) + 0.999f);
        int j0 = (int)u0, j1 = (int)u1;
        float t0 = u0 - (float)j0, t1 = u1 - (float)j1;
        const float* bp = d_T + (j1 - 1) * TSTRIDE + (j0 - 1);
        float v[16];
#pragma unroll
        for (int rr = 0; rr < 4; rr++)
#pragma unroll
            for (int cc = 0; cc < 4; cc++)
                v[rr * 4 + cc] = __ldg(bp + rr * TSTRIDE + cc);
        float am = t0 - 1.f, bm = t0 - 2.f, cp = t0 + 1.f;
        float wx0 = -t0 * am * bm * (1.f / 6.f);
        float wx1 = cp * am * bm * 0.5f;
        float wx2 = -cp * t0 * bm * 0.5f;
        float wx3 = cp * t0 * am * (1.f / 6.f);
        am = t1 - 1.f; bm = t1 - 2.f; cp = t1 + 1.f;
        float wy0 = -t1 * am * bm * (1.f / 6.f);
        float wy1 = cp * am * bm * 0.5f;
        float wy2 = -cp * t1 * bm * 0.5f;
        float wy3 = cp * t1 * am * (1.f / 6.f);
        float r0 = fmaf(wx0, v[0],  fmaf(wx1, v[1],  fmaf(wx2, v[2],  wx3 * v[3])));
        float r1 = fmaf(wx0, v[4],  fmaf(wx1, v[5],  fmaf(wx2, v[6],  wx3 * v[7])));
        float r2 = fmaf(wx0, v[8],  fmaf(wx1, v[9],  fmaf(wx2, v[10], wx3 * v[11])));
        float r3 = fmaf(wx0, v[12], fmaf(wx1, v[13], fmaf(wx2, v[14], wx3 * v[15])));
        out[n0] = fmaf(wy0, r0, fmaf(wy1, r1, fmaf(wy2, r2, wy3 * r3)));
    }
}

extern "C" void kernel_launch(void* const* d_in, const int* in_sizes, int n_in,
                              void* d_out, int out_size) {
    const float* X     = (const float*)d_in[0];
    const float* Wk0   = (const float*)d_in[1];
    const float* W10   = (const float*)d_in[2];
    const float* W21   = (const float*)d_in[3];
    const float* mu    = (const float*)d_in[4];
    const float* sigma = (const float*)d_in[5];
    int N = in_sizes[0] / 2;

    build_T_kernel<<<16, 1024>>>(Wk0, W10, W21, mu, sigma);

    int nthreads = (N + 1) / 2;
    int nb = (nthreads + 127) / 128;
    interp_kernel<<<nb, 128>>>((const float4*)X, (const float2*)X,
                               (float*)d_out, N);
}